// round 1
// baseline (speedup 1.0000x reference)
#include <cuda_runtime.h>
#include <cuda_bf16.h>

#define D 128
#define NMAX 50000

// Scratch (allocation-free rule: __device__ globals)
__device__ float g_A[(size_t)NMAX * D];   // GEMM output h for current layer
__device__ float g_B[(size_t)NMAX * D];   // aggregated layer output
__device__ float g_dinv[NMAX];            // rsqrt(degree)

// ---------------- degree / norm ----------------
__global__ void deg_init(float* __restrict__ dinv, int n) {
    int i = blockIdx.x * blockDim.x + threadIdx.x;
    if (i < n) dinv[i] = 1.0f;  // self-loop contributes 1
}

__global__ void deg_count(const int* __restrict__ dst, int e, float* __restrict__ dinv) {
    int i = blockIdx.x * blockDim.x + threadIdx.x;
    if (i < e) atomicAdd(&dinv[dst[i]], 1.0f);
}

__global__ void deg_finalize(float* __restrict__ dinv, int n) {
    int i = blockIdx.x * blockDim.x + threadIdx.x;
    if (i < n) dinv[i] = rsqrtf(fmaxf(dinv[i], 1.0f));
}

// ---------------- GEMM: Out[n,128] = act(X)[n,128] @ W[128,128] ----------------
// Block: 32 rows x 128 cols, 128 threads, thread tile 8 rows x 4 cols.
__global__ void __launch_bounds__(128) gemm_relu(
    const float* __restrict__ X, const float* __restrict__ W,
    float* __restrict__ Out, int n, int relu_in)
{
    __shared__ float sW[32 * 128];   // k-tile of W (rows kt..kt+31, all 128 cols)
    __shared__ float sX[32 * 32];    // 32 rows x 32 k

    const int tid = threadIdx.x;
    const int cb  = (tid & 31) * 4;       // column base (0..124)
    const int rb  = (tid >> 5) * 8;       // row base within tile (0,8,16,24)
    const int row0 = blockIdx.x * 32;

    float acc[8][4];
    #pragma unroll
    for (int r = 0; r < 8; r++)
        #pragma unroll
        for (int c = 0; c < 4; c++) acc[r][c] = 0.0f;

    for (int kt = 0; kt < 128; kt += 32) {
        // load W tile (flat copy: 1024 float4s)
        const float4* Wg = (const float4*)&W[kt * 128];
        float4* Ws4 = (float4*)sW;
        #pragma unroll
        for (int i = 0; i < 8; i++) Ws4[i * 128 + tid] = Wg[i * 128 + tid];

        // load X tile: 32 rows x 32 cols = 256 float4s
        #pragma unroll
        for (int i = 0; i < 2; i++) {
            int f4 = i * 128 + tid;        // 0..255
            int r  = f4 >> 3;              // 8 float4 per row
            int cc = (f4 & 7) * 4;
            float4 v = make_float4(0.f, 0.f, 0.f, 0.f);
            if (row0 + r < n)
                v = *(const float4*)&X[(size_t)(row0 + r) * 128 + kt + cc];
            if (relu_in) {
                v.x = fmaxf(v.x, 0.f); v.y = fmaxf(v.y, 0.f);
                v.z = fmaxf(v.z, 0.f); v.w = fmaxf(v.w, 0.f);
            }
            *(float4*)&sX[r * 32 + cc] = v;
        }
        __syncthreads();

        #pragma unroll
        for (int k = 0; k < 32; k++) {
            float4 w = *(const float4*)&sW[k * 128 + cb];
            #pragma unroll
            for (int r = 0; r < 8; r++) {
                float xv = sX[(rb + r) * 32 + k];
                acc[r][0] += xv * w.x;
                acc[r][1] += xv * w.y;
                acc[r][2] += xv * w.z;
                acc[r][3] += xv * w.w;
            }
        }
        __syncthreads();
    }

    #pragma unroll
    for (int r = 0; r < 8; r++) {
        int row = row0 + rb + r;
        if (row < n)
            *(float4*)&Out[(size_t)row * 128 + cb] =
                make_float4(acc[r][0], acc[r][1], acc[r][2], acc[r][3]);
    }
}

// ---------------- B[i] = bias + A[i] * dinv[i]^2 (self-loop fused) ----------------
__global__ void self_bias(const float* __restrict__ A, const float* __restrict__ bias,
                          const float* __restrict__ dinv, float* __restrict__ B, int n)
{
    int idx = blockIdx.x * blockDim.x + threadIdx.x;   // over n*32 float4s
    if (idx >= n * 32) return;
    int i = idx >> 5, c = idx & 31;
    float dv = dinv[i]; dv *= dv;
    float4 a = ((const float4*)A)[idx];
    float4 b = ((const float4*)bias)[c];
    ((float4*)B)[idx] = make_float4(b.x + a.x * dv, b.y + a.y * dv,
                                    b.z + a.z * dv, b.w + a.w * dv);
}

// ---------------- scatter: B[dst] += A[src] * dinv[src]*dinv[dst] ----------------
// one warp per edge; lane handles 4 contiguous floats
__global__ void __launch_bounds__(256) scatter_edges(
    const float* __restrict__ A, const int* __restrict__ src,
    const int* __restrict__ dst, const float* __restrict__ dinv,
    float* __restrict__ B, int e)
{
    int g = blockIdx.x * blockDim.x + threadIdx.x;
    int w = g >> 5, lane = g & 31;
    if (w >= e) return;
    int s = __ldg(&src[w]);
    int d = __ldg(&dst[w]);
    float nrm = __ldg(&dinv[s]) * __ldg(&dinv[d]);
    float4 h = ((const float4*)A)[(size_t)s * 32 + lane];
    float* bp = &B[(size_t)d * 128 + lane * 4];
    atomicAdd(bp + 0, h.x * nrm);
    atomicAdd(bp + 1, h.y * nrm);
    atomicAdd(bp + 2, h.z * nrm);
    atomicAdd(bp + 3, h.w * nrm);
}

// ---------------- decoder: out[e] = dot(X[u], X[v]) ----------------
__global__ void __launch_bounds__(256) decode_edges(
    const float* __restrict__ X, const int* __restrict__ U,
    const int* __restrict__ V, float* __restrict__ out, int el)
{
    int g = blockIdx.x * blockDim.x + threadIdx.x;
    int w = g >> 5, lane = g & 31;
    if (w >= el) return;
    int u = __ldg(&U[w]);
    int v = __ldg(&V[w]);
    float4 a = ((const float4*)X)[(size_t)u * 32 + lane];
    float4 b = ((const float4*)X)[(size_t)v * 32 + lane];
    float s = a.x * b.x + a.y * b.y + a.z * b.z + a.w * b.w;
    #pragma unroll
    for (int o = 16; o; o >>= 1) s += __shfl_xor_sync(0xffffffff, s, o);
    if (lane == 0) out[w] = s;
}

// ---------------- launch ----------------
extern "C" void kernel_launch(void* const* d_in, const int* in_sizes, int n_in,
                              void* d_out, int out_size)
{
    const float* nf = (const float*)d_in[0];
    const float* W1 = (const float*)d_in[1];
    const float* b1 = (const float*)d_in[2];
    const float* W2 = (const float*)d_in[3];
    const float* b2 = (const float*)d_in[4];
    const float* W3 = (const float*)d_in[5];
    const float* b3 = (const float*)d_in[6];
    const int* ei  = (const int*)d_in[7];   // [2, E]
    const int* eli = (const int*)d_in[8];   // [2, EL]
    float* out = (float*)d_out;

    const int N  = in_sizes[0] / D;
    const int E  = in_sizes[7] / 2;
    const int EL = in_sizes[8] / 2;

    float *A, *B, *dinv;
    cudaGetSymbolAddress((void**)&A, g_A);
    cudaGetSymbolAddress((void**)&B, g_B);
    cudaGetSymbolAddress((void**)&dinv, g_dinv);

    const int* e_src = ei;
    const int* e_dst = ei + E;

    // degree + dinv
    deg_init<<<(N + 255) / 256, 256>>>(dinv, N);
    deg_count<<<(E + 255) / 256, 256>>>(e_dst, E, dinv);
    deg_finalize<<<(N + 255) / 256, 256>>>(dinv, N);

    const int gemm_grid = (N + 31) / 32;
    const int sb_grid   = (N * 32 + 255) / 256;
    const int sc_blocks = (E * 32 + 255) / 256;

    // layer 1: A = nf @ W1 ; B = b1 + selfloop + scatter
    gemm_relu<<<gemm_grid, 128>>>(nf, W1, A, N, 0);
    self_bias<<<sb_grid, 256>>>(A, b1, dinv, B, N);
    scatter_edges<<<sc_blocks, 256>>>(A, e_src, e_dst, dinv, B, E);

    // layer 2: A = relu(B) @ W2 ; B = ...
    gemm_relu<<<gemm_grid, 128>>>(B, W2, A, N, 1);
    self_bias<<<sb_grid, 256>>>(A, b2, dinv, B, N);
    scatter_edges<<<sc_blocks, 256>>>(A, e_src, e_dst, dinv, B, E);

    // layer 3: no output relu
    gemm_relu<<<gemm_grid, 128>>>(B, W3, A, N, 1);
    self_bias<<<sb_grid, 256>>>(A, b3, dinv, B, N);
    scatter_edges<<<sc_blocks, 256>>>(A, e_src, e_dst, dinv, B, E);

    // decoder
    decode_edges<<<(EL * 32 + 255) / 256, 256>>>(B, eli, eli + EL, out, EL);
}

// round 3
// speedup vs baseline: 2.5128x; 2.5128x over previous
#include <cuda_runtime.h>
#include <cuda_bf16.h>

#define D 128
#define NMAX 50000
#define EMAX 800000

// Scratch (allocation-free rule: __device__ globals)
__device__ float g_A[(size_t)NMAX * D];     // GEMM output h for current layer
__device__ float g_B[(size_t)NMAX * D];     // aggregated layer output
__device__ float g_dinv[NMAX];              // rsqrt(degree)
__device__ int   g_cnt[NMAX];               // in-degree counts (excl self-loop)
__device__ int   g_cnt2[NMAX];              // fill cursors
__device__ int   g_rowptr[NMAX + 1];        // CSR row pointers (by dst)
__device__ int   g_col[EMAX];               // CSR: src node per edge
__device__ float g_coef[EMAX];              // CSR: dinv[src]*dinv[dst]

// ---------------- degree ----------------
__global__ void zero_cnt(int* __restrict__ cnt, int n) {
    int i = blockIdx.x * blockDim.x + threadIdx.x;
    if (i < n) cnt[i] = 0;
}

__global__ void count_dst(const int* __restrict__ dst, int e, int* __restrict__ cnt) {
    int i = blockIdx.x * blockDim.x + threadIdx.x;
    if (i < e) atomicAdd(&cnt[dst[i]], 1);
}

__global__ void dinv_from_cnt(const int* __restrict__ cnt, float* __restrict__ dinv, int n) {
    int i = blockIdx.x * blockDim.x + threadIdx.x;
    if (i < n) dinv[i] = rsqrtf((float)(cnt[i] + 1));   // +1 self-loop; deg>=1 always
}

// ---------------- single-block exclusive scan -> rowptr, reset cursors ----------------
__global__ void __launch_bounds__(1024) scan_build(
    const int* __restrict__ cnt, int* __restrict__ rowptr,
    int* __restrict__ cnt2, int n)
{
    __shared__ int spart[1024];
    const int t = threadIdx.x;
    const int chunk = (n + 1023) >> 10;
    const int lo = t * chunk;
    const int hi = min(lo + chunk, n);

    int s = 0;
    for (int i = lo; i < hi; i++) s += cnt[i];
    spart[t] = s;
    __syncthreads();
    // Hillis-Steele inclusive scan over partials
    for (int off = 1; off < 1024; off <<= 1) {
        int v = (t >= off) ? spart[t - off] : 0;
        __syncthreads();
        spart[t] += v;
        __syncthreads();
    }
    int run = (t > 0) ? spart[t - 1] : 0;   // exclusive prefix of this chunk
    for (int i = lo; i < hi; i++) {
        rowptr[i] = run;
        run += cnt[i];
        cnt2[i] = 0;
    }
    if (t == 1023) rowptr[n] = spart[1023];
}

// ---------------- fill CSR ----------------
__global__ void fill_csr(
    const int* __restrict__ src, const int* __restrict__ dst, int e,
    const int* __restrict__ rowptr, int* __restrict__ cnt2,
    const float* __restrict__ dinv, int* __restrict__ col, float* __restrict__ coef)
{
    int i = blockIdx.x * blockDim.x + threadIdx.x;
    if (i >= e) return;
    int s = src[i], d = dst[i];
    int pos = rowptr[d] + atomicAdd(&cnt2[d], 1);
    col[pos]  = s;
    coef[pos] = __ldg(&dinv[s]) * __ldg(&dinv[d]);
}

// ---------------- GEMM: Out[n,128] = act(X)[n,128] @ W[128,128] ----------------
__global__ void __launch_bounds__(128) gemm_relu(
    const float* __restrict__ X, const float* __restrict__ W,
    float* __restrict__ Out, int n, int relu_in)
{
    __shared__ float sW[32 * 128];
    __shared__ float sX[32 * 32];

    const int tid = threadIdx.x;
    const int cb  = (tid & 31) * 4;
    const int rb  = (tid >> 5) * 8;
    const int row0 = blockIdx.x * 32;

    float acc[8][4];
    #pragma unroll
    for (int r = 0; r < 8; r++)
        #pragma unroll
        for (int c = 0; c < 4; c++) acc[r][c] = 0.0f;

    for (int kt = 0; kt < 128; kt += 32) {
        const float4* Wg = (const float4*)&W[kt * 128];
        float4* Ws4 = (float4*)sW;
        #pragma unroll
        for (int i = 0; i < 8; i++) Ws4[i * 128 + tid] = Wg[i * 128 + tid];

        #pragma unroll
        for (int i = 0; i < 2; i++) {
            int f4 = i * 128 + tid;
            int r  = f4 >> 3;
            int cc = (f4 & 7) * 4;
            float4 v = make_float4(0.f, 0.f, 0.f, 0.f);
            if (row0 + r < n)
                v = *(const float4*)&X[(size_t)(row0 + r) * 128 + kt + cc];
            if (relu_in) {
                v.x = fmaxf(v.x, 0.f); v.y = fmaxf(v.y, 0.f);
                v.z = fmaxf(v.z, 0.f); v.w = fmaxf(v.w, 0.f);
            }
            *(float4*)&sX[r * 32 + cc] = v;
        }
        __syncthreads();

        #pragma unroll
        for (int k = 0; k < 32; k++) {
            float4 w = *(const float4*)&sW[k * 128 + cb];
            #pragma unroll
            for (int r = 0; r < 8; r++) {
                float xv = sX[(rb + r) * 32 + k];
                acc[r][0] += xv * w.x;
                acc[r][1] += xv * w.y;
                acc[r][2] += xv * w.z;
                acc[r][3] += xv * w.w;
            }
        }
        __syncthreads();
    }

    #pragma unroll
    for (int r = 0; r < 8; r++) {
        int row = row0 + rb + r;
        if (row < n)
            *(float4*)&Out[(size_t)row * 128 + cb] =
                make_float4(acc[r][0], acc[r][1], acc[r][2], acc[r][3]);
    }
}

// ---------------- CSR gather: B[i] = bias + A[i]*dinv[i]^2 + sum_j A[col[j]]*coef[j] ----------------
// one warp per node; lane handles 4 contiguous floats
__global__ void __launch_bounds__(256) gather_nodes(
    const float* __restrict__ A, const int* __restrict__ rowptr,
    const int* __restrict__ col, const float* __restrict__ coef,
    const float* __restrict__ bias, const float* __restrict__ dinv,
    float* __restrict__ B, int n)
{
    int g = blockIdx.x * blockDim.x + threadIdx.x;
    int node = g >> 5, lane = g & 31;
    if (node >= n) return;

    float dv = __ldg(&dinv[node]); dv *= dv;
    float4 a  = ((const float4*)A)[(size_t)node * 32 + lane];
    float4 bb = ((const float4*)bias)[lane];
    float4 acc = make_float4(bb.x + a.x * dv, bb.y + a.y * dv,
                             bb.z + a.z * dv, bb.w + a.w * dv);

    int j   = __ldg(&rowptr[node]);
    int end = __ldg(&rowptr[node + 1]);

    // unroll by 2 for load-level parallelism
    for (; j + 1 < end; j += 2) {
        int s0 = __ldg(&col[j]);
        int s1 = __ldg(&col[j + 1]);
        float c0 = __ldg(&coef[j]);
        float c1 = __ldg(&coef[j + 1]);
        float4 h0 = ((const float4*)A)[(size_t)s0 * 32 + lane];
        float4 h1 = ((const float4*)A)[(size_t)s1 * 32 + lane];
        acc.x += h0.x * c0; acc.y += h0.y * c0;
        acc.z += h0.z * c0; acc.w += h0.w * c0;
        acc.x += h1.x * c1; acc.y += h1.y * c1;
        acc.z += h1.z * c1; acc.w += h1.w * c1;
    }
    if (j < end) {
        int s0 = __ldg(&col[j]);
        float c0 = __ldg(&coef[j]);
        float4 h0 = ((const float4*)A)[(size_t)s0 * 32 + lane];
        acc.x += h0.x * c0; acc.y += h0.y * c0;
        acc.z += h0.z * c0; acc.w += h0.w * c0;
    }

    ((float4*)B)[(size_t)node * 32 + lane] = acc;
}

// ---------------- decoder: out[e] = dot(X[u], X[v]) ----------------
__global__ void __launch_bounds__(256) decode_edges(
    const float* __restrict__ X, const int* __restrict__ U,
    const int* __restrict__ V, float* __restrict__ out, int el)
{
    int g = blockIdx.x * blockDim.x + threadIdx.x;
    int w = g >> 5, lane = g & 31;
    if (w >= el) return;
    int u = __ldg(&U[w]);
    int v = __ldg(&V[w]);
    float4 a = ((const float4*)X)[(size_t)u * 32 + lane];
    float4 b = ((const float4*)X)[(size_t)v * 32 + lane];
    float s = a.x * b.x + a.y * b.y + a.z * b.z + a.w * b.w;
    #pragma unroll
    for (int o = 16; o; o >>= 1) s += __shfl_xor_sync(0xffffffff, s, o);
    if (lane == 0) out[w] = s;
}

// ---------------- launch ----------------
extern "C" void kernel_launch(void* const* d_in, const int* in_sizes, int n_in,
                              void* d_out, int out_size)
{
    const float* nf = (const float*)d_in[0];
    const float* W1 = (const float*)d_in[1];
    const float* b1 = (const float*)d_in[2];
    const float* W2 = (const float*)d_in[3];
    const float* b2 = (const float*)d_in[4];
    const float* W3 = (const float*)d_in[5];
    const float* b3 = (const float*)d_in[6];
    const int* ei  = (const int*)d_in[7];   // [2, E]
    const int* eli = (const int*)d_in[8];   // [2, EL]
    float* out = (float*)d_out;

    const int N  = in_sizes[0] / D;
    const int E  = in_sizes[7] / 2;
    const int EL = in_sizes[8] / 2;

    float *A, *B, *dinv, *coef;
    int *cnt, *cnt2, *rowptr, *col;
    cudaGetSymbolAddress((void**)&A, g_A);
    cudaGetSymbolAddress((void**)&B, g_B);
    cudaGetSymbolAddress((void**)&dinv, g_dinv);
    cudaGetSymbolAddress((void**)&cnt, g_cnt);
    cudaGetSymbolAddress((void**)&cnt2, g_cnt2);
    cudaGetSymbolAddress((void**)&rowptr, g_rowptr);
    cudaGetSymbolAddress((void**)&col, g_col);
    cudaGetSymbolAddress((void**)&coef, g_coef);

    const int* e_src = ei;
    const int* e_dst = ei + E;

    // ---- CSR build ----
    zero_cnt<<<(N + 255) / 256, 256>>>(cnt, N);
    count_dst<<<(E + 255) / 256, 256>>>(e_dst, E, cnt);
    dinv_from_cnt<<<(N + 255) / 256, 256>>>(cnt, dinv, N);
    scan_build<<<1, 1024>>>(cnt, rowptr, cnt2, N);
    fill_csr<<<(E + 255) / 256, 256>>>(e_src, e_dst, E, rowptr, cnt2, dinv, col, coef);

    const int gemm_grid = (N + 31) / 32;
    const int gn_grid   = (N * 32 + 255) / 256;

    // layer 1
    gemm_relu<<<gemm_grid, 128>>>(nf, W1, A, N, 0);
    gather_nodes<<<gn_grid, 256>>>(A, rowptr, col, coef, b1, dinv, B, N);
    // layer 2
    gemm_relu<<<gemm_grid, 128>>>(B, W2, A, N, 1);
    gather_nodes<<<gn_grid, 256>>>(A, rowptr, col, coef, b2, dinv, B, N);
    // layer 3
    gemm_relu<<<gemm_grid, 128>>>(B, W3, A, N, 1);
    gather_nodes<<<gn_grid, 256>>>(A, rowptr, col, coef, b3, dinv, B, N);

    // decoder
    decode_edges<<<(EL * 32 + 255) / 256, 256>>>(B, eli, eli + EL, out, EL);
}

// round 4
// speedup vs baseline: 3.1462x; 1.2521x over previous
#include <cuda_runtime.h>
#include <cuda_bf16.h>

#define D 128
#define NMAX 50000
#define EMAX 800000
#define SCAN_CHUNK 1024
#define NBMAX 64   // ceil(NMAX/SCAN_CHUNK) = 49 <= 64

// Scratch (allocation-free rule: __device__ globals)
__device__ float g_A[(size_t)NMAX * D];     // GEMM output h for current layer
__device__ float g_B[(size_t)NMAX * D];     // aggregated layer output
__device__ float g_dinv[NMAX];              // rsqrt(degree)
__device__ int   g_cnt[NMAX];               // in-degree counts (excl self-loop)
__device__ int   g_cnt2[NMAX];              // fill cursors
__device__ int   g_rowptr[NMAX + 1];        // CSR row pointers (by dst)
__device__ int   g_col[EMAX];               // CSR: src node per edge
__device__ float g_coef[EMAX];              // CSR: dinv[src]*dinv[dst]
__device__ int   g_part[NBMAX];             // block partial sums
__device__ int   g_base[NBMAX];             // exclusive block bases

// ---------------- degree ----------------
__global__ void zero_cnt(int* __restrict__ cnt, int n) {
    int i = blockIdx.x * blockDim.x + threadIdx.x;
    if (i < n) cnt[i] = 0;
}

__global__ void count_dst(const int* __restrict__ dst, int e, int* __restrict__ cnt) {
    int i = blockIdx.x * blockDim.x + threadIdx.x;
    if (i < e) atomicAdd(&cnt[dst[i]], 1);
}

// ---------------- scan phase 1: per-block (1024 elems) partial sums ----------------
__global__ void __launch_bounds__(256) partial_sums(
    const int* __restrict__ cnt, int n, int* __restrict__ part)
{
    __shared__ int sm[256];
    const int t = threadIdx.x;
    const int i0 = blockIdx.x * SCAN_CHUNK + t * 4;
    int s = 0;
    #pragma unroll
    for (int k = 0; k < 4; k++)
        if (i0 + k < n) s += cnt[i0 + k];
    sm[t] = s;
    __syncthreads();
    #pragma unroll
    for (int off = 128; off; off >>= 1) {
        if (t < off) sm[t] += sm[t + off];
        __syncthreads();
    }
    if (t == 0) part[blockIdx.x] = sm[0];
}

// ---------------- scan phase 2: scan <=64 partials, write rowptr[n] ----------------
__global__ void scan_partials(const int* __restrict__ part, int nb,
                              int* __restrict__ base, int* __restrict__ rowptr, int n)
{
    __shared__ int sm[NBMAX];
    const int t = threadIdx.x;   // 64 threads
    sm[t] = (t < nb) ? part[t] : 0;
    __syncthreads();
    #pragma unroll
    for (int off = 1; off < NBMAX; off <<= 1) {
        int v = (t >= off) ? sm[t - off] : 0;
        __syncthreads();
        sm[t] += v;
        __syncthreads();
    }
    base[t] = (t == 0) ? 0 : sm[t - 1];
    if (t == 0) rowptr[n] = sm[nb - 1];
}

// ---------------- scan phase 3: per-block scan -> rowptr, reset cnt2, compute dinv ----------------
__global__ void __launch_bounds__(256) write_rowptr(
    const int* __restrict__ cnt, const int* __restrict__ base, int n,
    int* __restrict__ rowptr, int* __restrict__ cnt2, float* __restrict__ dinv)
{
    __shared__ int sm[256];
    const int t = threadIdx.x;
    const int i0 = blockIdx.x * SCAN_CHUNK + t * 4;
    int c[4]; int s = 0;
    #pragma unroll
    for (int k = 0; k < 4; k++) {
        c[k] = (i0 + k < n) ? cnt[i0 + k] : 0;
        s += c[k];
    }
    sm[t] = s;
    __syncthreads();
    #pragma unroll
    for (int off = 1; off < 256; off <<= 1) {
        int v = (t >= off) ? sm[t - off] : 0;
        __syncthreads();
        sm[t] += v;
        __syncthreads();
    }
    int run = base[blockIdx.x] + ((t > 0) ? sm[t - 1] : 0);
    #pragma unroll
    for (int k = 0; k < 4; k++) {
        if (i0 + k < n) {
            rowptr[i0 + k] = run;
            run += c[k];
            cnt2[i0 + k] = 0;
            dinv[i0 + k] = rsqrtf((float)(c[k] + 1));  // +1 self-loop
        }
    }
}

// ---------------- fill CSR ----------------
__global__ void fill_csr(
    const int* __restrict__ src, const int* __restrict__ dst, int e,
    const int* __restrict__ rowptr, int* __restrict__ cnt2,
    const float* __restrict__ dinv, int* __restrict__ col, float* __restrict__ coef)
{
    int i = blockIdx.x * blockDim.x + threadIdx.x;
    if (i >= e) return;
    int s = src[i], d = dst[i];
    int pos = rowptr[d] + atomicAdd(&cnt2[d], 1);
    col[pos]  = s;
    coef[pos] = __ldg(&dinv[s]) * __ldg(&dinv[d]);
}

// ---------------- GEMM: Out[n,128] = act(X)[n,128] @ W[128,128] ----------------
__global__ void __launch_bounds__(128) gemm_relu(
    const float* __restrict__ X, const float* __restrict__ W,
    float* __restrict__ Out, int n, int relu_in)
{
    __shared__ float sW[32 * 128];
    __shared__ float sX[32 * 32];

    const int tid = threadIdx.x;
    const int cb  = (tid & 31) * 4;
    const int rb  = (tid >> 5) * 8;
    const int row0 = blockIdx.x * 32;

    float acc[8][4];
    #pragma unroll
    for (int r = 0; r < 8; r++)
        #pragma unroll
        for (int c = 0; c < 4; c++) acc[r][c] = 0.0f;

    for (int kt = 0; kt < 128; kt += 32) {
        const float4* Wg = (const float4*)&W[kt * 128];
        float4* Ws4 = (float4*)sW;
        #pragma unroll
        for (int i = 0; i < 8; i++) Ws4[i * 128 + tid] = Wg[i * 128 + tid];

        #pragma unroll
        for (int i = 0; i < 2; i++) {
            int f4 = i * 128 + tid;
            int r  = f4 >> 3;
            int cc = (f4 & 7) * 4;
            float4 v = make_float4(0.f, 0.f, 0.f, 0.f);
            if (row0 + r < n)
                v = *(const float4*)&X[(size_t)(row0 + r) * 128 + kt + cc];
            if (relu_in) {
                v.x = fmaxf(v.x, 0.f); v.y = fmaxf(v.y, 0.f);
                v.z = fmaxf(v.z, 0.f); v.w = fmaxf(v.w, 0.f);
            }
            *(float4*)&sX[r * 32 + cc] = v;
        }
        __syncthreads();

        #pragma unroll
        for (int k = 0; k < 32; k++) {
            float4 w = *(const float4*)&sW[k * 128 + cb];
            #pragma unroll
            for (int r = 0; r < 8; r++) {
                float xv = sX[(rb + r) * 32 + k];
                acc[r][0] += xv * w.x;
                acc[r][1] += xv * w.y;
                acc[r][2] += xv * w.z;
                acc[r][3] += xv * w.w;
            }
        }
        __syncthreads();
    }

    #pragma unroll
    for (int r = 0; r < 8; r++) {
        int row = row0 + rb + r;
        if (row < n)
            *(float4*)&Out[(size_t)row * 128 + cb] =
                make_float4(acc[r][0], acc[r][1], acc[r][2], acc[r][3]);
    }
}

// ---------------- CSR gather: B[i] = bias + A[i]*dinv[i]^2 + sum_j A[col[j]]*coef[j] ----------------
// one warp per node; lane handles 4 contiguous floats; 4-wide unroll for MLP
__global__ void __launch_bounds__(256) gather_nodes(
    const float* __restrict__ A, const int* __restrict__ rowptr,
    const int* __restrict__ col, const float* __restrict__ coef,
    const float* __restrict__ bias, const float* __restrict__ dinv,
    float* __restrict__ B, int n)
{
    int g = blockIdx.x * blockDim.x + threadIdx.x;
    int node = g >> 5, lane = g & 31;
    if (node >= n) return;

    float dv = __ldg(&dinv[node]); dv *= dv;
    float4 a  = ((const float4*)A)[(size_t)node * 32 + lane];
    float4 bb = ((const float4*)bias)[lane];
    float4 acc = make_float4(bb.x + a.x * dv, bb.y + a.y * dv,
                             bb.z + a.z * dv, bb.w + a.w * dv);

    int j   = __ldg(&rowptr[node]);
    int end = __ldg(&rowptr[node + 1]);

    for (; j + 3 < end; j += 4) {
        int   s0 = __ldg(&col[j]),     s1 = __ldg(&col[j + 1]);
        int   s2 = __ldg(&col[j + 2]), s3 = __ldg(&col[j + 3]);
        float c0 = __ldg(&coef[j]),     c1 = __ldg(&coef[j + 1]);
        float c2 = __ldg(&coef[j + 2]), c3 = __ldg(&coef[j + 3]);
        float4 h0 = ((const float4*)A)[(size_t)s0 * 32 + lane];
        float4 h1 = ((const float4*)A)[(size_t)s1 * 32 + lane];
        float4 h2 = ((const float4*)A)[(size_t)s2 * 32 + lane];
        float4 h3 = ((const float4*)A)[(size_t)s3 * 32 + lane];
        acc.x += h0.x * c0; acc.y += h0.y * c0; acc.z += h0.z * c0; acc.w += h0.w * c0;
        acc.x += h1.x * c1; acc.y += h1.y * c1; acc.z += h1.z * c1; acc.w += h1.w * c1;
        acc.x += h2.x * c2; acc.y += h2.y * c2; acc.z += h2.z * c2; acc.w += h2.w * c2;
        acc.x += h3.x * c3; acc.y += h3.y * c3; acc.z += h3.z * c3; acc.w += h3.w * c3;
    }
    for (; j < end; j++) {
        int s0 = __ldg(&col[j]);
        float c0 = __ldg(&coef[j]);
        float4 h0 = ((const float4*)A)[(size_t)s0 * 32 + lane];
        acc.x += h0.x * c0; acc.y += h0.y * c0; acc.z += h0.z * c0; acc.w += h0.w * c0;
    }

    ((float4*)B)[(size_t)node * 32 + lane] = acc;
}

// ---------------- decoder: out[e] = dot(X[u], X[v]) ----------------
__global__ void __launch_bounds__(256) decode_edges(
    const float* __restrict__ X, const int* __restrict__ U,
    const int* __restrict__ V, float* __restrict__ out, int el)
{
    int g = blockIdx.x * blockDim.x + threadIdx.x;
    int w = g >> 5, lane = g & 31;
    if (w >= el) return;
    int u = __ldg(&U[w]);
    int v = __ldg(&V[w]);
    float4 a = ((const float4*)X)[(size_t)u * 32 + lane];
    float4 b = ((const float4*)X)[(size_t)v * 32 + lane];
    float s = a.x * b.x + a.y * b.y + a.z * b.z + a.w * b.w;
    #pragma unroll
    for (int o = 16; o; o >>= 1) s += __shfl_xor_sync(0xffffffff, s, o);
    if (lane == 0) out[w] = s;
}

// ---------------- launch ----------------
extern "C" void kernel_launch(void* const* d_in, const int* in_sizes, int n_in,
                              void* d_out, int out_size)
{
    const float* nf = (const float*)d_in[0];
    const float* W1 = (const float*)d_in[1];
    const float* b1 = (const float*)d_in[2];
    const float* W2 = (const float*)d_in[3];
    const float* b2 = (const float*)d_in[4];
    const float* W3 = (const float*)d_in[5];
    const float* b3 = (const float*)d_in[6];
    const int* ei  = (const int*)d_in[7];   // [2, E]
    const int* eli = (const int*)d_in[8];   // [2, EL]
    float* out = (float*)d_out;

    const int N  = in_sizes[0] / D;
    const int E  = in_sizes[7] / 2;
    const int EL = in_sizes[8] / 2;

    float *A, *B, *dinv, *coef;
    int *cnt, *cnt2, *rowptr, *col, *part, *base;
    cudaGetSymbolAddress((void**)&A, g_A);
    cudaGetSymbolAddress((void**)&B, g_B);
    cudaGetSymbolAddress((void**)&dinv, g_dinv);
    cudaGetSymbolAddress((void**)&cnt, g_cnt);
    cudaGetSymbolAddress((void**)&cnt2, g_cnt2);
    cudaGetSymbolAddress((void**)&rowptr, g_rowptr);
    cudaGetSymbolAddress((void**)&col, g_col);
    cudaGetSymbolAddress((void**)&coef, g_coef);
    cudaGetSymbolAddress((void**)&part, g_part);
    cudaGetSymbolAddress((void**)&base, g_base);

    const int* e_src = ei;
    const int* e_dst = ei + E;
    const int nb = (N + SCAN_CHUNK - 1) / SCAN_CHUNK;

    // ---- CSR build (full-chip scan pipeline) ----
    zero_cnt<<<(N + 255) / 256, 256>>>(cnt, N);
    count_dst<<<(E + 255) / 256, 256>>>(e_dst, E, cnt);
    partial_sums<<<nb, 256>>>(cnt, N, part);
    scan_partials<<<1, NBMAX>>>(part, nb, base, rowptr, N);
    write_rowptr<<<nb, 256>>>(cnt, base, N, rowptr, cnt2, dinv);
    fill_csr<<<(E + 255) / 256, 256>>>(e_src, e_dst, E, rowptr, cnt2, dinv, col, coef);

    const int gemm_grid = (N + 31) / 32;
    const int gn_grid   = (N * 32 + 255) / 256;

    // layer 1
    gemm_relu<<<gemm_grid, 128>>>(nf, W1, A, N, 0);
    gather_nodes<<<gn_grid, 256>>>(A, rowptr, col, coef, b1, dinv, B, N);
    // layer 2
    gemm_relu<<<gemm_grid, 128>>>(B, W2, A, N, 1);
    gather_nodes<<<gn_grid, 256>>>(A, rowptr, col, coef, b2, dinv, B, N);
    // layer 3
    gemm_relu<<<gemm_grid, 128>>>(B, W3, A, N, 1);
    gather_nodes<<<gn_grid, 256>>>(A, rowptr, col, coef, b3, dinv, B, N);

    // decoder
    decode_edges<<<(EL * 32 + 255) / 256, 256>>>(B, eli, eli + EL, out, EL);
}

// round 6
// speedup vs baseline: 3.3313x; 1.0588x over previous
#include <cuda_runtime.h>
#include <cuda_bf16.h>

#define D 128
#define NMAX 50000
#define EMAX 800000
#define SCAN_CHUNK 1024
#define NBMAX 64
#define LDW 136   // padded bf16 row stride (128 + 8) -> conflict-free LDSM

// Scratch (allocation-free rule: __device__ globals)
__device__ float g_A[(size_t)NMAX * D];
__device__ float g_B[(size_t)NMAX * D];
__device__ float g_dinv[NMAX];
__device__ int   g_cnt[NMAX];
__device__ int   g_cnt2[NMAX];
__device__ int   g_rowptr[NMAX + 1];
__device__ int   g_col[EMAX];
__device__ float g_coef[EMAX];
__device__ int   g_part[NBMAX];
__device__ int   g_base[NBMAX];

// ---------------- degree ----------------
__global__ void zero_cnt(int* __restrict__ cnt, int n) {
    int i = blockIdx.x * blockDim.x + threadIdx.x;
    if (i < n) cnt[i] = 0;
}

__global__ void count_dst(const int* __restrict__ dst, int e, int* __restrict__ cnt) {
    int i = blockIdx.x * blockDim.x + threadIdx.x;
    if (i < e) atomicAdd(&cnt[dst[i]], 1);
}

// ---------------- scan phase 1 ----------------
__global__ void __launch_bounds__(256) partial_sums(
    const int* __restrict__ cnt, int n, int* __restrict__ part)
{
    __shared__ int sm[256];
    const int t = threadIdx.x;
    const int i0 = blockIdx.x * SCAN_CHUNK + t * 4;
    int s = 0;
    #pragma unroll
    for (int k = 0; k < 4; k++)
        if (i0 + k < n) s += cnt[i0 + k];
    sm[t] = s;
    __syncthreads();
    #pragma unroll
    for (int off = 128; off; off >>= 1) {
        if (t < off) sm[t] += sm[t + off];
        __syncthreads();
    }
    if (t == 0) part[blockIdx.x] = sm[0];
}

// ---------------- scan phase 2 ----------------
__global__ void scan_partials(const int* __restrict__ part, int nb,
                              int* __restrict__ base, int* __restrict__ rowptr, int n)
{
    __shared__ int sm[NBMAX];
    const int t = threadIdx.x;
    sm[t] = (t < nb) ? part[t] : 0;
    __syncthreads();
    #pragma unroll
    for (int off = 1; off < NBMAX; off <<= 1) {
        int v = (t >= off) ? sm[t - off] : 0;
        __syncthreads();
        sm[t] += v;
        __syncthreads();
    }
    base[t] = (t == 0) ? 0 : sm[t - 1];
    if (t == 0) rowptr[n] = sm[nb - 1];
}

// ---------------- scan phase 3 ----------------
__global__ void __launch_bounds__(256) write_rowptr(
    const int* __restrict__ cnt, const int* __restrict__ base, int n,
    int* __restrict__ rowptr, int* __restrict__ cnt2, float* __restrict__ dinv)
{
    __shared__ int sm[256];
    const int t = threadIdx.x;
    const int i0 = blockIdx.x * SCAN_CHUNK + t * 4;
    int c[4]; int s = 0;
    #pragma unroll
    for (int k = 0; k < 4; k++) {
        c[k] = (i0 + k < n) ? cnt[i0 + k] : 0;
        s += c[k];
    }
    sm[t] = s;
    __syncthreads();
    #pragma unroll
    for (int off = 1; off < 256; off <<= 1) {
        int v = (t >= off) ? sm[t - off] : 0;
        __syncthreads();
        sm[t] += v;
        __syncthreads();
    }
    int run = base[blockIdx.x] + ((t > 0) ? sm[t - 1] : 0);
    #pragma unroll
    for (int k = 0; k < 4; k++) {
        if (i0 + k < n) {
            rowptr[i0 + k] = run;
            run += c[k];
            cnt2[i0 + k] = 0;
            dinv[i0 + k] = rsqrtf((float)(c[k] + 1));
        }
    }
}

// ---------------- fill CSR ----------------
__global__ void fill_csr(
    const int* __restrict__ src, const int* __restrict__ dst, int e,
    const int* __restrict__ rowptr, int* __restrict__ cnt2,
    const float* __restrict__ dinv, int* __restrict__ col, float* __restrict__ coef)
{
    int i = blockIdx.x * blockDim.x + threadIdx.x;
    if (i >= e) return;
    int s = src[i], d = dst[i];
    int pos = rowptr[d] + atomicAdd(&cnt2[d], 1);
    col[pos]  = s;
    coef[pos] = __ldg(&dinv[s]) * __ldg(&dinv[d]);
}

// ---------------- split-bf16 tensor-core GEMM ----------------
// Out[n,128] = act(X)[n,128] @ W[128,128], 3-product bf16 split (~fp32 accuracy).
// Block: 128 rows, 256 threads (8 warps), warp tile 16x128.

__device__ __forceinline__ void mma16816(float* c, const unsigned* a, const unsigned* b) {
    asm volatile(
        "mma.sync.aligned.m16n8k16.row.col.f32.bf16.bf16.f32 "
        "{%0,%1,%2,%3}, {%4,%5,%6,%7}, {%8,%9}, {%0,%1,%2,%3};"
        : "+f"(c[0]), "+f"(c[1]), "+f"(c[2]), "+f"(c[3])
        : "r"(a[0]), "r"(a[1]), "r"(a[2]), "r"(a[3]), "r"(b[0]), "r"(b[1]));
}

__device__ __forceinline__ void ldsm4(unsigned* d, unsigned addr) {
    asm volatile("ldmatrix.sync.aligned.m8n8.x4.shared.b16 {%0,%1,%2,%3}, [%4];"
        : "=r"(d[0]), "=r"(d[1]), "=r"(d[2]), "=r"(d[3]) : "r"(addr));
}

__device__ __forceinline__ void ldsm4t(unsigned* d, unsigned addr) {
    asm volatile("ldmatrix.sync.aligned.m8n8.x4.trans.shared.b16 {%0,%1,%2,%3}, [%4];"
        : "=r"(d[0]), "=r"(d[1]), "=r"(d[2]), "=r"(d[3]) : "r"(addr));
}

__device__ __forceinline__ void split2(float x, __nv_bfloat16& h, __nv_bfloat16& l) {
    h = __float2bfloat16(x);
    l = __float2bfloat16(x - __bfloat162float(h));
}

extern __shared__ __nv_bfloat16 smem_dyn[];

__global__ void __launch_bounds__(256) gemm_bf16_split(
    const float* __restrict__ X, const float* __restrict__ W,
    float* __restrict__ Out, int n, int relu_in)
{
    __nv_bfloat16* sXhi = smem_dyn;
    __nv_bfloat16* sXlo = sXhi + 128 * LDW;
    __nv_bfloat16* sWhi = sXlo + 128 * LDW;
    __nv_bfloat16* sWlo = sWhi + 128 * LDW;

    const int tid  = threadIdx.x;
    const int row0 = blockIdx.x * 128;

    // ---- load & split-convert W[128,128] and X rows [row0, row0+128) ----
    for (int i = tid; i < 128 * 32; i += 256) {       // i over float4s
        int r = i >> 5, c = (i & 31) * 4;
        float4 wv = *(const float4*)&W[r * 128 + c];
        __nv_bfloat16 h, l;
        split2(wv.x, h, l); sWhi[r*LDW + c+0] = h; sWlo[r*LDW + c+0] = l;
        split2(wv.y, h, l); sWhi[r*LDW + c+1] = h; sWlo[r*LDW + c+1] = l;
        split2(wv.z, h, l); sWhi[r*LDW + c+2] = h; sWlo[r*LDW + c+2] = l;
        split2(wv.w, h, l); sWhi[r*LDW + c+3] = h; sWlo[r*LDW + c+3] = l;

        float4 xv = make_float4(0.f, 0.f, 0.f, 0.f);
        if (row0 + r < n)
            xv = *(const float4*)&X[(size_t)(row0 + r) * 128 + c];
        if (relu_in) {
            xv.x = fmaxf(xv.x, 0.f); xv.y = fmaxf(xv.y, 0.f);
            xv.z = fmaxf(xv.z, 0.f); xv.w = fmaxf(xv.w, 0.f);
        }
        split2(xv.x, h, l); sXhi[r*LDW + c+0] = h; sXlo[r*LDW + c+0] = l;
        split2(xv.y, h, l); sXhi[r*LDW + c+1] = h; sXlo[r*LDW + c+1] = l;
        split2(xv.z, h, l); sXhi[r*LDW + c+2] = h; sXlo[r*LDW + c+2] = l;
        split2(xv.w, h, l); sXhi[r*LDW + c+3] = h; sXlo[r*LDW + c+3] = l;
    }
    __syncthreads();

    const int warp = tid >> 5, lane = tid & 31;
    const int mrow = warp * 16;

    unsigned sXhi_u = (unsigned)__cvta_generic_to_shared(sXhi);
    unsigned sXlo_u = (unsigned)__cvta_generic_to_shared(sXlo);
    unsigned sWhi_u = (unsigned)__cvta_generic_to_shared(sWhi);
    unsigned sWlo_u = (unsigned)__cvta_generic_to_shared(sWlo);

    float acc[16][4];
    #pragma unroll
    for (int t = 0; t < 16; t++)
        #pragma unroll
        for (int k = 0; k < 4; k++) acc[t][k] = 0.0f;

    const int lq = (lane & 7) + ((lane >> 3) & 1) * 8;   // row within 16
    const int lh = (lane >> 4) * 8;                      // 8-col half select

    #pragma unroll
    for (int kt = 0; kt < 8; kt++) {
        unsigned aoff = ((mrow + lq) * LDW + kt * 16 + lh) * 2;
        unsigned ahi[4], alo[4];
        ldsm4(ahi, sXhi_u + aoff);
        ldsm4(alo, sXlo_u + aoff);

        const int br = kt * 16 + lq;
        #pragma unroll
        for (int np = 0; np < 8; np++) {
            unsigned boff = (br * LDW + np * 16 + lh) * 2;
            unsigned bhi[4], blo[4];
            ldsm4t(bhi, sWhi_u + boff);
            ldsm4t(blo, sWlo_u + boff);
            mma16816(acc[np*2],     ahi, bhi);
            mma16816(acc[np*2],     ahi, blo);
            mma16816(acc[np*2],     alo, bhi);
            mma16816(acc[np*2+1],   ahi, bhi + 2);
            mma16816(acc[np*2+1],   ahi, blo + 2);
            mma16816(acc[np*2+1],   alo, bhi + 2);
        }
    }

    // ---- epilogue: c frag (t/4, 2*(t%4)) / (+8 rows) ----
    const int r0 = row0 + mrow + (lane >> 2);
    const int c0 = (lane & 3) * 2;
    #pragma unroll
    for (int t = 0; t < 16; t++) {
        int c = t * 8 + c0;
        if (r0 < n)
            *(float2*)&Out[(size_t)r0 * 128 + c] = make_float2(acc[t][0], acc[t][1]);
        if (r0 + 8 < n)
            *(float2*)&Out[(size_t)(r0 + 8) * 128 + c] = make_float2(acc[t][2], acc[t][3]);
    }
}

// ---------------- CSR gather ----------------
__global__ void __launch_bounds__(256) gather_nodes(
    const float* __restrict__ A, const int* __restrict__ rowptr,
    const int* __restrict__ col, const float* __restrict__ coef,
    const float* __restrict__ bias, const float* __restrict__ dinv,
    float* __restrict__ B, int n)
{
    int g = blockIdx.x * blockDim.x + threadIdx.x;
    int node = g >> 5, lane = g & 31;
    if (node >= n) return;

    float dv = __ldg(&dinv[node]); dv *= dv;
    float4 a  = ((const float4*)A)[(size_t)node * 32 + lane];
    float4 bb = ((const float4*)bias)[lane];
    float4 acc = make_float4(bb.x + a.x * dv, bb.y + a.y * dv,
                             bb.z + a.z * dv, bb.w + a.w * dv);

    int j   = __ldg(&rowptr[node]);
    int end = __ldg(&rowptr[node + 1]);

    for (; j + 3 < end; j += 4) {
        int   s0 = __ldg(&col[j]),     s1 = __ldg(&col[j + 1]);
        int   s2 = __ldg(&col[j + 2]), s3 = __ldg(&col[j + 3]);
        float c0 = __ldg(&coef[j]),     c1 = __ldg(&coef[j + 1]);
        float c2 = __ldg(&coef[j + 2]), c3 = __ldg(&coef[j + 3]);
        float4 h0 = ((const float4*)A)[(size_t)s0 * 32 + lane];
        float4 h1 = ((const float4*)A)[(size_t)s1 * 32 + lane];
        float4 h2 = ((const float4*)A)[(size_t)s2 * 32 + lane];
        float4 h3 = ((const float4*)A)[(size_t)s3 * 32 + lane];
        acc.x += h0.x * c0; acc.y += h0.y * c0; acc.z += h0.z * c0; acc.w += h0.w * c0;
        acc.x += h1.x * c1; acc.y += h1.y * c1; acc.z += h1.z * c1; acc.w += h1.w * c1;
        acc.x += h2.x * c2; acc.y += h2.y * c2; acc.z += h2.z * c2; acc.w += h2.w * c2;
        acc.x += h3.x * c3; acc.y += h3.y * c3; acc.z += h3.z * c3; acc.w += h3.w * c3;
    }
    for (; j < end; j++) {
        int s0 = __ldg(&col[j]);
        float c0 = __ldg(&coef[j]);
        float4 h0 = ((const float4*)A)[(size_t)s0 * 32 + lane];
        acc.x += h0.x * c0; acc.y += h0.y * c0; acc.z += h0.z * c0; acc.w += h0.w * c0;
    }

    ((float4*)B)[(size_t)node * 32 + lane] = acc;
}

// ---------------- decoder ----------------
__global__ void __launch_bounds__(256) decode_edges(
    const float* __restrict__ X, const int* __restrict__ U,
    const int* __restrict__ V, float* __restrict__ out, int el)
{
    int g = blockIdx.x * blockDim.x + threadIdx.x;
    int w = g >> 5, lane = g & 31;
    if (w >= el) return;
    int u = __ldg(&U[w]);
    int v = __ldg(&V[w]);
    float4 a = ((const float4*)X)[(size_t)u * 32 + lane];
    float4 b = ((const float4*)X)[(size_t)v * 32 + lane];
    float s = a.x * b.x + a.y * b.y + a.z * b.z + a.w * b.w;
    #pragma unroll
    for (int o = 16; o; o >>= 1) s += __shfl_xor_sync(0xffffffff, s, o);
    if (lane == 0) out[w] = s;
}

// ---------------- launch ----------------
extern "C" void kernel_launch(void* const* d_in, const int* in_sizes, int n_in,
                              void* d_out, int out_size)
{
    const float* nf = (const float*)d_in[0];
    const float* W1 = (const float*)d_in[1];
    const float* b1 = (const float*)d_in[2];
    const float* W2 = (const float*)d_in[3];
    const float* b2 = (const float*)d_in[4];
    const float* W3 = (const float*)d_in[5];
    const float* b3 = (const float*)d_in[6];
    const int* ei  = (const int*)d_in[7];
    const int* eli = (const int*)d_in[8];
    float* out = (float*)d_out;

    const int N  = in_sizes[0] / D;
    const int E  = in_sizes[7] / 2;
    const int EL = in_sizes[8] / 2;

    float *A, *B, *dinv, *coef;
    int *cnt, *cnt2, *rowptr, *col, *part, *base;
    cudaGetSymbolAddress((void**)&A, g_A);
    cudaGetSymbolAddress((void**)&B, g_B);
    cudaGetSymbolAddress((void**)&dinv, g_dinv);
    cudaGetSymbolAddress((void**)&cnt, g_cnt);
    cudaGetSymbolAddress((void**)&cnt2, g_cnt2);
    cudaGetSymbolAddress((void**)&rowptr, g_rowptr);
    cudaGetSymbolAddress((void**)&col, g_col);
    cudaGetSymbolAddress((void**)&coef, g_coef);
    cudaGetSymbolAddress((void**)&part, g_part);
    cudaGetSymbolAddress((void**)&base, g_base);

    const int* e_src = ei;
    const int* e_dst = ei + E;
    const int nb = (N + SCAN_CHUNK - 1) / SCAN_CHUNK;

    const int smem_gemm = 4 * 128 * LDW * (int)sizeof(__nv_bfloat16);  // 139264
    cudaFuncSetAttribute(gemm_bf16_split,
                         cudaFuncAttributeMaxDynamicSharedMemorySize, smem_gemm);

    // ---- CSR build ----
    zero_cnt<<<(N + 255) / 256, 256>>>(cnt, N);
    count_dst<<<(E + 255) / 256, 256>>>(e_dst, E, cnt);
    partial_sums<<<nb, 256>>>(cnt, N, part);
    scan_partials<<<1, NBMAX>>>(part, nb, base, rowptr, N);
    write_rowptr<<<nb, 256>>>(cnt, base, N, rowptr, cnt2, dinv);
    fill_csr<<<(E + 255) / 256, 256>>>(e_src, e_dst, E, rowptr, cnt2, dinv, col, coef);

    const int gemm_grid = (N + 127) / 128;
    const int gn_grid   = (N * 32 + 255) / 256;

    // layer 1
    gemm_bf16_split<<<gemm_grid, 256, smem_gemm>>>(nf, W1, A, N, 0);
    gather_nodes<<<gn_grid, 256>>>(A, rowptr, col, coef, b1, dinv, B, N);
    // layer 2
    gemm_bf16_split<<<gemm_grid, 256, smem_gemm>>>(B, W2, A, N, 1);
    gather_nodes<<<gn_grid, 256>>>(A, rowptr, col, coef, b2, dinv, B, N);
    // layer 3
    gemm_bf16_split<<<gemm_grid, 256, smem_gemm>>>(B, W3, A, N, 1);
    gather_nodes<<<gn_grid, 256>>>(A, rowptr, col, coef, b3, dinv, B, N);

    // decoder
    decode_edges<<<(EL * 32 + 255) / 256, 256>>>(B, eli, eli + EL, out, EL);
}